// round 1
// baseline (speedup 1.0000x reference)
#include <cuda_runtime.h>

#define NQ 10
#define NL 3
#define DIM 1024          // 2^NQ amplitudes
#define THREADS 256       // 4 amplitudes / thread, 2 gate-pairs / thread

__global__ __launch_bounds__(THREADS)
void qnn_kernel(const float* __restrict__ x,      // (B, 10)
                const float* __restrict__ w,      // (3, 10, 3)
                float* __restrict__ out)          // (B, 10)
{
    __shared__ float2 st[DIM];                    // statevector (re, im)
    __shared__ float4 gsh[NL * NQ * 2];           // fused gates: 2x float4 per gate
    __shared__ float  wsum[8][NQ];                // per-warp partial <Z_q>

    const int tid = threadIdx.x;
    const int b   = blockIdx.x;

    // ---- init |0...0> ----
    #pragma unroll
    for (int r = 0; r < 4; r++)
        st[tid + r * THREADS] = make_float2(0.f, 0.f);
    if (tid == 0) st[0] = make_float2(1.f, 0.f);

    // ---- precompute fused gates G = Rot(phi,theta,omega) @ RY(x_q) ----
    // Rot = [[e^{-i a} ch, -e^{ i b} sh],
    //        [e^{-i b} sh,  e^{ i a} ch]],  a=(phi+om)/2, b=(phi-om)/2
    if (tid < NL * NQ) {
        const int q = tid % NQ;
        const float  xv = x[b * NQ + q];
        const float* wp = w + tid * 3;            // (l*NQ+q)*3
        const float phi = wp[0], th = wp[1], om = wp[2];
        float s, c;   sincosf(0.5f * xv, &s, &c);
        float sh, ch; sincosf(0.5f * th, &sh, &ch);
        float sa, ca; sincosf(0.5f * (phi + om), &sa, &ca);
        float sb, cb; sincosf(0.5f * (phi - om), &sb, &cb);
        const float m00x =  ca * ch, m00y = -sa * ch;
        const float m01x = -cb * sh, m01y = -sb * sh;
        const float m10x =  cb * sh, m10y = -sb * sh;
        const float m11x =  ca * ch, m11y =  sa * ch;
        // G = Rot * [[c,-s],[s,c]]   (c,s real)
        gsh[tid * 2 + 0] = make_float4( m00x * c + m01x * s,  m00y * c + m01y * s,
                                       -m00x * s + m01x * c, -m00y * s + m01y * c);
        gsh[tid * 2 + 1] = make_float4( m10x * c + m11x * s,  m10y * c + m11y * s,
                                       -m10x * s + m11x * c, -m10y * s + m11y * c);
    }
    __syncthreads();

    // ---- circuit ----
    #pragma unroll
    for (int l = 0; l < NL; l++) {
        // 10 fused single-qubit gates
        #pragma unroll
        for (int q = 0; q < NQ; q++) {
            const int bbit = 9 - q;               // qubit q lives at bit (9-q)
            const int mask = 1 << bbit;
            const float4 g0 = gsh[(l * NQ + q) * 2 + 0];
            const float4 g1 = gsh[(l * NQ + q) * 2 + 1];
            #pragma unroll
            for (int r = 0; r < 2; r++) {
                const int p  = tid + r * THREADS;                     // pair id 0..511
                const int i0 = ((p >> bbit) << (bbit + 1)) | (p & (mask - 1));
                const int i1 = i0 | mask;
                const float2 a0 = st[i0];
                const float2 a1 = st[i1];
                float2 n0, n1;
                n0.x = g0.x * a0.x - g0.y * a0.y + g0.z * a1.x - g0.w * a1.y;
                n0.y = g0.x * a0.y + g0.y * a0.x + g0.z * a1.y + g0.w * a1.x;
                n1.x = g1.x * a0.x - g1.y * a0.y + g1.z * a1.x - g1.w * a1.y;
                n1.y = g1.x * a0.y + g1.y * a0.x + g1.z * a1.y + g1.w * a1.x;
                st[i0] = n0;
                st[i1] = n1;
            }
            __syncthreads();
        }

        // CNOT ring (q -> q+1 mod 10) collapsed into one basis permutation.
        // Forward map F = C9∘...∘C0 (C0 first). new[j] = old[F^{-1}(j)],
        // F^{-1} applies C9 first, then C8, ..., then C0 (each CNOT self-inverse).
        float2 tmp[4];
        #pragma unroll
        for (int r = 0; r < 4; r++) {
            const int j = tid + r * THREADS;
            int src = j;
            #pragma unroll
            for (int qq = 9; qq >= 0; qq--) {
                const int cbit = 9 - qq;
                const int tbit = 9 - ((qq + 1) % NQ);
                if ((src >> cbit) & 1) src ^= (1 << tbit);
            }
            tmp[r] = st[src];
        }
        __syncthreads();
        #pragma unroll
        for (int r = 0; r < 4; r++)
            st[tid + r * THREADS] = tmp[r];
        __syncthreads();
    }

    // ---- <Z_q> = sum_i |a_i|^2 * (bit(9-q,i) ? -1 : +1) ----
    float z[NQ];
    #pragma unroll
    for (int q = 0; q < NQ; q++) z[q] = 0.f;
    #pragma unroll
    for (int r = 0; r < 4; r++) {
        const int i = tid + r * THREADS;
        const float2 a = st[i];
        const float p = a.x * a.x + a.y * a.y;
        #pragma unroll
        for (int q = 0; q < NQ; q++)
            z[q] += ((i >> (9 - q)) & 1) ? -p : p;
    }
    // warp-level tree reduce (deterministic)
    #pragma unroll
    for (int q = 0; q < NQ; q++) {
        #pragma unroll
        for (int o = 16; o > 0; o >>= 1)
            z[q] += __shfl_xor_sync(0xffffffffu, z[q], o);
    }
    const int warp = tid >> 5;
    if ((tid & 31) == 0) {
        #pragma unroll
        for (int q = 0; q < NQ; q++) wsum[warp][q] = z[q];
    }
    __syncthreads();
    if (tid < NQ) {
        float acc = 0.f;
        #pragma unroll
        for (int wi = 0; wi < 8; wi++) acc += wsum[wi][tid];
        out[b * NQ + tid] = acc;
    }
}

extern "C" void kernel_launch(void* const* d_in, const int* in_sizes, int n_in,
                              void* d_out, int out_size)
{
    const float* x = (const float*)d_in[0];       // (B, 10) float32
    const float* w = (const float*)d_in[1];       // (3, 10, 3) float32
    float* out = (float*)d_out;                   // (B, 10) float32
    const int B = in_sizes[0] / NQ;
    qnn_kernel<<<B, THREADS>>>(x, w, out);
}

// round 2
// speedup vs baseline: 2.1026x; 2.1026x over previous
#include <cuda_runtime.h>

#define NQ 10
#define NL 3
#define DIM 1024
#define NT 64
#define R  16

// XOR swizzle: conflict-free for all six smem access patterns used below.
__device__ __forceinline__ int swz(int i) { return i ^ ((i >> 4) & 0xF); }

// Apply fused 2x2 complex gate on register-bit P of the 4-bit register index.
template<int P>
__device__ __forceinline__ void apply_gate(float2* a, const float4* gg, int gi)
{
    const float4 g0 = gg[gi * 2 + 0];
    const float4 g1 = gg[gi * 2 + 1];
#pragma unroll
    for (int k = 0; k < R / 2; k++) {
        const int r0 = ((k >> P) << (P + 1)) | (k & ((1 << P) - 1));
        const int r1 = r0 | (1 << P);
        const float2 a0 = a[r0];
        const float2 a1 = a[r1];
        float2 n0, n1;
        n0.x = g0.x * a0.x - g0.y * a0.y + g0.z * a1.x - g0.w * a1.y;
        n0.y = g0.x * a0.y + g0.y * a0.x + g0.z * a1.y + g0.w * a1.x;
        n1.x = g1.x * a0.x - g1.y * a0.y + g1.z * a1.x - g1.w * a1.y;
        n1.y = g1.x * a0.y + g1.y * a0.x + g1.z * a1.y + g1.w * a1.x;
        a[r0] = n0;
        a[r1] = n1;
    }
}

__global__ __launch_bounds__(NT)
void qnn_kernel(const float* __restrict__ x,      // (B, 10)
                const float* __restrict__ w,      // (3, 10, 3)
                float* __restrict__ out)          // (B, 10)
{
    __shared__ float2 st[DIM];                    // swizzled statevector
    __shared__ float4 gg[NL * NQ * 2];            // fused gates
    __shared__ float  wsum[2][NQ];

    const int tid = threadIdx.x;
    const int b   = blockIdx.x;

    // ---- state in registers: layout A, i = (r<<6) | tid ----
    float2 a[R];
#pragma unroll
    for (int r = 0; r < R; r++) a[r] = make_float2(0.f, 0.f);
    if (tid == 0) a[0].x = 1.f;                   // |0...0>

    // ---- precompute fused gates G = Rot(phi,theta,omega) @ RY(x_q) ----
    if (tid < NL * NQ) {
        const int q = tid % NQ;
        const float xv  = x[b * NQ + q];
        const float phi = w[tid * 3 + 0];
        const float th  = w[tid * 3 + 1];
        const float om  = w[tid * 3 + 2];
        float s, c;   sincosf(0.5f * xv, &s, &c);
        float sh, ch; sincosf(0.5f * th, &sh, &ch);
        float sa, ca; sincosf(0.5f * (phi + om), &sa, &ca);
        float sb, cb; sincosf(0.5f * (phi - om), &sb, &cb);
        const float m00x =  ca * ch, m00y = -sa * ch;
        const float m01x = -cb * sh, m01y = -sb * sh;
        const float m10x =  cb * sh, m10y = -sb * sh;
        const float m11x =  ca * ch, m11y =  sa * ch;
        gg[tid * 2 + 0] = make_float4( m00x * c + m01x * s,  m00y * c + m01y * s,
                                      -m00x * s + m01x * c, -m00y * s + m01y * c);
        gg[tid * 2 + 1] = make_float4( m10x * c + m11x * s,  m10y * c + m11y * s,
                                      -m10x * s + m11x * c, -m10y * s + m11y * c);
    }
    __syncthreads();

#pragma unroll 1
    for (int l = 0; l < NL; l++) {
        const int gb = l * NQ;

        // Layout A: i-bits 9..6 in registers -> qubits 0..3 (i-bit 9-q)
        apply_gate<3>(a, gg, gb + 0);
        apply_gate<2>(a, gg, gb + 1);
        apply_gate<1>(a, gg, gb + 2);
        apply_gate<0>(a, gg, gb + 3);

        // T1: A -> B  (B: i = (tid<<4) | r)
        __syncthreads();
#pragma unroll
        for (int r = 0; r < R; r++) st[swz((r << 6) | tid)] = a[r];
        __syncthreads();
#pragma unroll
        for (int r = 0; r < R; r++) a[r] = st[swz((tid << 4) | r)];

        // Layout B: i-bits 3..0 in registers -> qubits 9..6
        apply_gate<0>(a, gg, gb + 9);
        apply_gate<1>(a, gg, gb + 8);
        apply_gate<2>(a, gg, gb + 7);
        apply_gate<3>(a, gg, gb + 6);

        // T2: B -> C  (C: r bits = i bits {4,5,8,9}, tid bits = i bits {0..3,6,7})
        __syncthreads();
#pragma unroll
        for (int r = 0; r < R; r++) st[swz((tid << 4) | r)] = a[r];
        __syncthreads();
#pragma unroll
        for (int r = 0; r < R; r++) {
            const int i = (tid & 0xF) | ((r & 3) << 4)
                        | (((tid >> 4) & 3) << 6) | ((r >> 2) << 8);
            a[r] = st[swz(i)];
        }

        // Layout C: qubit 4 (i-bit 5 -> r-bit 1), qubit 5 (i-bit 4 -> r-bit 0)
        apply_gate<1>(a, gg, gb + 4);
        apply_gate<0>(a, gg, gb + 5);

        // T3: store C, gather through CNOT-ring permutation back to layout A.
        // src(j) = j ^ (j>>1) ^ ((j&1) ? 0x300 : 0)   [closed form of the ring]
        __syncthreads();
#pragma unroll
        for (int r = 0; r < R; r++) {
            const int i = (tid & 0xF) | ((r & 3) << 4)
                        | (((tid >> 4) & 3) << 6) | ((r >> 2) << 8);
            st[swz(i)] = a[r];
        }
        __syncthreads();
#pragma unroll
        for (int r = 0; r < R; r++) {
            const int j = (r << 6) | tid;
            int src = j ^ (j >> 1);
            if (j & 1) src ^= 0x300;
            a[r] = st[swz(src)];
        }
    }

    // ---- readout: <Z_q>, layout A (i = (r<<6)|tid) ----
    float p[R];
#pragma unroll
    for (int r = 0; r < R; r++) p[r] = a[r].x * a[r].x + a[r].y * a[r].y;

    float t = 0.f;
#pragma unroll
    for (int r = 0; r < R; r++) t += p[r];

    float z[NQ];
#pragma unroll
    for (int q = 0; q < 4; q++) {                 // sign from r bits (compile-time)
        float s = 0.f;
#pragma unroll
        for (int r = 0; r < R; r++)
            s += ((r >> (3 - q)) & 1) ? -p[r] : p[r];
        z[q] = s;
    }
#pragma unroll
    for (int q = 4; q < NQ; q++)                  // sign from tid bits (uniform over r)
        z[q] = ((tid >> (9 - q)) & 1) ? -t : t;

#pragma unroll
    for (int q = 0; q < NQ; q++) {
#pragma unroll
        for (int o = 16; o > 0; o >>= 1)
            z[q] += __shfl_xor_sync(0xffffffffu, z[q], o);
    }
    if ((tid & 31) == 0) {
#pragma unroll
        for (int q = 0; q < NQ; q++) wsum[tid >> 5][q] = z[q];
    }
    __syncthreads();
    if (tid < NQ) out[b * NQ + tid] = wsum[0][tid] + wsum[1][tid];
}

extern "C" void kernel_launch(void* const* d_in, const int* in_sizes, int n_in,
                              void* d_out, int out_size)
{
    const float* x = (const float*)d_in[0];       // (B, 10) float32
    const float* w = (const float*)d_in[1];       // (3, 10, 3) float32
    float* out = (float*)d_out;                   // (B, 10) float32
    const int B = in_sizes[0] / NQ;
    qnn_kernel<<<B, NT>>>(x, w, out);
}

// round 3
// speedup vs baseline: 2.2030x; 1.0477x over previous
#include <cuda_runtime.h>

#define NQ 10
#define NL 3
#define DIM 1024
#define NT 64
#define R  16

typedef unsigned long long u64;

// ---- packed f32x2 helpers (sm_103a) ----
__device__ __forceinline__ u64 pack2(float x, float y) {
    u64 r; asm("mov.b64 %0, {%1,%2};" : "=l"(r) : "f"(x), "f"(y)); return r;
}
__device__ __forceinline__ void unpack2(u64 v, float& x, float& y) {
    asm("mov.b64 {%0,%1}, %2;" : "=f"(x), "=f"(y) : "l"(v));
}
__device__ __forceinline__ u64 swap2(u64 v) {
    float x, y; unpack2(v, x, y); return pack2(y, x);
}
__device__ __forceinline__ u64 fma2(u64 a, u64 b, u64 c) {
    u64 d; asm("fma.rn.f32x2 %0, %1, %2, %3;" : "=l"(d) : "l"(a), "l"(b), "l"(c)); return d;
}
__device__ __forceinline__ u64 mul2(u64 a, u64 b) {
    u64 d; asm("mul.rn.f32x2 %0, %1, %2;" : "=l"(d) : "l"(a), "l"(b)); return d;
}

// XOR swizzle: conflict-free for all smem access patterns used below.
__device__ __forceinline__ int swz(int i) { return i ^ ((i >> 4) & 0xF); }

// Fused 2x2 complex gate on register-bit P, packed-f32x2 math.
// g[0..7] = G0x,G0y,G0z,G0w,G1x,G1y,G1z,G1w  (sign-folded packed constants)
template<int P>
__device__ __forceinline__ void apply_gate(u64* a, const u64* __restrict__ g)
{
    const u64 G0x = g[0], G0y = g[1], G0z = g[2], G0w = g[3];
    const u64 G1x = g[4], G1y = g[5], G1z = g[6], G1w = g[7];
#pragma unroll
    for (int k = 0; k < R / 2; k++) {
        const int r0 = ((k >> P) << (P + 1)) | (k & ((1 << P) - 1));
        const int r1 = r0 | (1 << P);
        const u64 a0  = a[r0];
        const u64 a1  = a[r1];
        const u64 a0s = swap2(a0);
        const u64 a1s = swap2(a1);
        a[r0] = fma2(G0x, a0, fma2(G0y, a0s, fma2(G0z, a1, mul2(G0w, a1s))));
        a[r1] = fma2(G1x, a0, fma2(G1y, a0s, fma2(G1z, a1, mul2(G1w, a1s))));
    }
}

__global__ __launch_bounds__(NT)
void qnn_kernel(const float* __restrict__ x,      // (B, 10)
                const float* __restrict__ w,      // (3, 10, 3)
                float* __restrict__ out)          // (B, 10)
{
    __shared__ u64 st[DIM];                       // swizzled statevector (packed re,im)
    __shared__ u64 gg[NL * NQ * 8];               // packed fused gates
    __shared__ float wsum[2][NQ];

    const int tid = threadIdx.x;
    const int b   = blockIdx.x;

    // ---- state in registers: layout A, i = (r<<6) | tid ----
    u64 a[R];
#pragma unroll
    for (int r = 0; r < R; r++) a[r] = 0ull;
    if (tid == 0) a[0] = pack2(1.f, 0.f);         // |0...0>

    // ---- precompute fused gates G = Rot(phi,theta,omega) @ RY(x_q), packed ----
    if (tid < NL * NQ) {
        const int q = tid % NQ;
        const float xv  = x[b * NQ + q];
        const float phi = w[tid * 3 + 0];
        const float th  = w[tid * 3 + 1];
        const float om  = w[tid * 3 + 2];
        float s, c;   sincosf(0.5f * xv, &s, &c);
        float sh, ch; sincosf(0.5f * th, &sh, &ch);
        float sa, ca; sincosf(0.5f * (phi + om), &sa, &ca);
        float sb, cb; sincosf(0.5f * (phi - om), &sb, &cb);
        const float m00x =  ca * ch, m00y = -sa * ch;
        const float m01x = -cb * sh, m01y = -sb * sh;
        const float m10x =  cb * sh, m10y = -sb * sh;
        const float m11x =  ca * ch, m11y =  sa * ch;
        // fuse with RY(x): G = Rot * [[c,-s],[s,c]]
        const float g0x =  m00x * c + m01x * s, g0y =  m00y * c + m01y * s;
        const float g0z = -m00x * s + m01x * c, g0w = -m00y * s + m01y * c;
        const float g1x =  m10x * c + m11x * s, g1y =  m10y * c + m11y * s;
        const float g1z = -m10x * s + m11x * c, g1w = -m10y * s + m11y * c;
        u64* gp = gg + tid * 8;
        gp[0] = pack2(g0x, g0x);  gp[1] = pack2(-g0y, g0y);
        gp[2] = pack2(g0z, g0z);  gp[3] = pack2(-g0w, g0w);
        gp[4] = pack2(g1x, g1x);  gp[5] = pack2(-g1y, g1y);
        gp[6] = pack2(g1z, g1z);  gp[7] = pack2(-g1w, g1w);
    }
    __syncthreads();

#pragma unroll 1
    for (int l = 0; l < NL; l++) {
        const u64* gb = gg + l * NQ * 8;

        // Layout A: i-bits 9..6 in registers -> qubits 0..3
        apply_gate<3>(a, gb + 0 * 8);
        apply_gate<2>(a, gb + 1 * 8);
        apply_gate<1>(a, gb + 2 * 8);
        apply_gate<0>(a, gb + 3 * 8);

        // T1: A -> B  (B: i = (tid<<4) | r)
        __syncthreads();
#pragma unroll
        for (int r = 0; r < R; r++) st[swz((r << 6) | tid)] = a[r];
        __syncthreads();
#pragma unroll
        for (int r = 0; r < R; r++) a[r] = st[swz((tid << 4) | r)];

        // Layout B: i-bits 3..0 in registers -> qubits 9..6
        apply_gate<0>(a, gb + 9 * 8);
        apply_gate<1>(a, gb + 8 * 8);
        apply_gate<2>(a, gb + 7 * 8);
        apply_gate<3>(a, gb + 6 * 8);

        // T2: B -> C  (C: r bits = i bits {4,5,8,9}, tid bits = i bits {0..3,6,7})
        __syncthreads();
#pragma unroll
        for (int r = 0; r < R; r++) st[swz((tid << 4) | r)] = a[r];
        __syncthreads();
#pragma unroll
        for (int r = 0; r < R; r++) {
            const int i = (tid & 0xF) | ((r & 3) << 4)
                        | (((tid >> 4) & 3) << 6) | ((r >> 2) << 8);
            a[r] = st[swz(i)];
        }

        // Layout C: qubit 4 (i-bit 5 -> r-bit 1), qubit 5 (i-bit 4 -> r-bit 0)
        apply_gate<1>(a, gb + 4 * 8);
        apply_gate<0>(a, gb + 5 * 8);

        // T3: store C, gather through CNOT-ring permutation back to layout A.
        // src(j) = j ^ (j>>1) ^ ((j&1) ? 0x300 : 0)
        __syncthreads();
#pragma unroll
        for (int r = 0; r < R; r++) {
            const int i = (tid & 0xF) | ((r & 3) << 4)
                        | (((tid >> 4) & 3) << 6) | ((r >> 2) << 8);
            st[swz(i)] = a[r];
        }
        __syncthreads();
#pragma unroll
        for (int r = 0; r < R; r++) {
            const int j = (r << 6) | tid;
            int src = j ^ (j >> 1);
            if (j & 1) src ^= 0x300;
            a[r] = st[swz(src)];
        }
    }

    // ---- readout: <Z_q>, layout A (i = (r<<6)|tid) ----
    float p[R];
#pragma unroll
    for (int r = 0; r < R; r++) {
        float xx, yy; unpack2(mul2(a[r], a[r]), xx, yy);
        p[r] = xx + yy;
    }

    float t = 0.f;
#pragma unroll
    for (int r = 0; r < R; r++) t += p[r];

    float z[NQ];
#pragma unroll
    for (int q = 0; q < 4; q++) {                 // sign from r bits (compile-time)
        float s = 0.f;
#pragma unroll
        for (int r = 0; r < R; r++)
            s += ((r >> (3 - q)) & 1) ? -p[r] : p[r];
        z[q] = s;
    }
#pragma unroll
    for (int q = 4; q < NQ; q++)                  // sign from tid bits (uniform over r)
        z[q] = ((tid >> (9 - q)) & 1) ? -t : t;

#pragma unroll
    for (int q = 0; q < NQ; q++) {
#pragma unroll
        for (int o = 16; o > 0; o >>= 1)
            z[q] += __shfl_xor_sync(0xffffffffu, z[q], o);
    }
    if ((tid & 31) == 0) {
#pragma unroll
        for (int q = 0; q < NQ; q++) wsum[tid >> 5][q] = z[q];
    }
    __syncthreads();
    if (tid < NQ) out[b * NQ + tid] = wsum[0][tid] + wsum[1][tid];
}

extern "C" void kernel_launch(void* const* d_in, const int* in_sizes, int n_in,
                              void* d_out, int out_size)
{
    const float* x = (const float*)d_in[0];       // (B, 10) float32
    const float* w = (const float*)d_in[1];       // (3, 10, 3) float32
    float* out = (float*)d_out;                   // (B, 10) float32
    const int B = in_sizes[0] / NQ;
    qnn_kernel<<<B, NT>>>(x, w, out);
}

// round 4
// speedup vs baseline: 2.6825x; 1.2177x over previous
#include <cuda_runtime.h>

#define NQ 10
#define NL 3
#define DIM 1024
#define NT 64
#define R  16

typedef unsigned long long u64;

// ---- packed f32x2 helpers (sm_103a) ----
__device__ __forceinline__ u64 pack2(float x, float y) {
    u64 r; asm("mov.b64 %0, {%1,%2};" : "=l"(r) : "f"(x), "f"(y)); return r;
}
__device__ __forceinline__ void unpack2(u64 v, float& x, float& y) {
    asm("mov.b64 {%0,%1}, %2;" : "=f"(x), "=f"(y) : "l"(v));
}
__device__ __forceinline__ u64 swap2(u64 v) {
    float x, y; unpack2(v, x, y); return pack2(y, x);
}
__device__ __forceinline__ u64 fma2(u64 a, u64 b, u64 c) {
    u64 d; asm("fma.rn.f32x2 %0, %1, %2, %3;" : "=l"(d) : "l"(a), "l"(b), "l"(c)); return d;
}
__device__ __forceinline__ u64 mul2(u64 a, u64 b) {
    u64 d; asm("mul.rn.f32x2 %0, %1, %2;" : "=l"(d) : "l"(a), "l"(b)); return d;
}

__device__ __forceinline__ float2 cmul(float2 a, float2 b) {
    float2 c;
    c.x = a.x * b.x - a.y * b.y;
    c.y = a.x * b.y + a.y * b.x;
    return c;
}

// XOR swizzle: conflict-free for all smem access patterns used below.
__device__ __forceinline__ int swz(int i) { return i ^ ((i >> 4) & 0xF); }

// layout-C index for (r, tid): r bits -> i bits {4,5,8,9}, tid bits -> {0..3,6,7}
__device__ __forceinline__ int idxC(int r, int tid) {
    return (tid & 0xF) | ((r & 3) << 4) | (((tid >> 4) & 3) << 6) | ((r >> 2) << 8);
}

// Fused 2x2 complex gate on register-bit P, packed-f32x2 math.
template<int P>
__device__ __forceinline__ void apply_gate(u64* a, const u64* __restrict__ g)
{
    const u64 G0x = g[0], G0y = g[1], G0z = g[2], G0w = g[3];
    const u64 G1x = g[4], G1y = g[5], G1z = g[6], G1w = g[7];
#pragma unroll
    for (int k = 0; k < R / 2; k++) {
        const int r0 = ((k >> P) << (P + 1)) | (k & ((1 << P) - 1));
        const int r1 = r0 | (1 << P);
        const u64 a0  = a[r0];
        const u64 a1  = a[r1];
        const u64 a0s = swap2(a0);
        const u64 a1s = swap2(a1);
        a[r0] = fma2(G0x, a0, fma2(G0y, a0s, fma2(G0z, a1, mul2(G0w, a1s))));
        a[r1] = fma2(G1x, a0, fma2(G1y, a0s, fma2(G1z, a1, mul2(G1w, a1s))));
    }
}

__global__ __launch_bounds__(NT)
void qnn_kernel(const float* __restrict__ x,      // (B, 10)
                const float* __restrict__ w,      // (3, 10, 3)
                float* __restrict__ out)          // (B, 10)
{
    __shared__ u64 st[DIM];                       // swizzled statevector
    __shared__ u64 gg[2 * NQ * 8];                // packed fused gates, layers 1,2
    __shared__ float2 vcol[NQ][2];                // layer-0 gate first columns
    __shared__ float wsum[2][NQ];

    const int tid = threadIdx.x;
    const int b   = blockIdx.x;

    // ---- precompute fused gates G = Rot(phi,theta,omega) @ RY(x_q) ----
    if (tid < NL * NQ) {
        const int q = tid % NQ;
        const float xv  = x[b * NQ + q];
        const float phi = w[tid * 3 + 0];
        const float th  = w[tid * 3 + 1];
        const float om  = w[tid * 3 + 2];
        float s, c;   sincosf(0.5f * xv, &s, &c);
        float sh, ch; sincosf(0.5f * th, &sh, &ch);
        float sa, ca; sincosf(0.5f * (phi + om), &sa, &ca);
        float sb, cb; sincosf(0.5f * (phi - om), &sb, &cb);
        const float m00x =  ca * ch, m00y = -sa * ch;
        const float m01x = -cb * sh, m01y = -sb * sh;
        const float m10x =  cb * sh, m10y = -sb * sh;
        const float m11x =  ca * ch, m11y =  sa * ch;
        const float g0x =  m00x * c + m01x * s, g0y =  m00y * c + m01y * s;
        const float g0z = -m00x * s + m01x * c, g0w = -m00y * s + m01y * c;
        const float g1x =  m10x * c + m11x * s, g1y =  m10y * c + m11y * s;
        const float g1z = -m10x * s + m11x * c, g1w = -m10y * s + m11y * c;
        if (tid < NQ) {
            // layer 0 acts on |0..0>: only column 0 needed
            vcol[tid][0] = make_float2(g0x, g0y);
            vcol[tid][1] = make_float2(g1x, g1y);
        } else {
            u64* gp = gg + (tid - NQ) * 8;
            gp[0] = pack2(g0x, g0x);  gp[1] = pack2(-g0y, g0y);
            gp[2] = pack2(g0z, g0z);  gp[3] = pack2(-g0w, g0w);
            gp[4] = pack2(g1x, g1x);  gp[5] = pack2(-g1y, g1y);
            gp[6] = pack2(g1z, g1z);  gp[7] = pack2(-g1w, g1w);
        }
    }
    __syncthreads();

    u64 a[R];

    // ---- layer 0: product state built directly in layout C ----
    // amp(i) = prod_k vcol[9-k][bit_k(i)]
    {
        const int c0 =  tid       & 1, c1 = (tid >> 1) & 1;
        const int c2 = (tid >> 2) & 1, c3 = (tid >> 3) & 1;
        const int c6 = (tid >> 4) & 1, c7 = (tid >> 5) & 1;
        const float2 Pt = cmul(cmul(cmul(vcol[9][c0], vcol[8][c1]),
                                    cmul(vcol[7][c2], vcol[6][c3])),
                               cmul(vcol[3][c6], vcol[2][c7]));
        float2 pq45[4], q89[4];
#pragma unroll
        for (int rr = 0; rr < 4; rr++) {
            pq45[rr] = cmul(Pt, cmul(vcol[5][rr & 1], vcol[4][rr >> 1]));
            q89[rr]  = cmul(vcol[1][rr & 1], vcol[0][rr >> 1]);
        }
#pragma unroll
        for (int r = 0; r < R; r++) {
            const float2 v = cmul(pq45[r & 3], q89[r >> 2]);
            a[r] = pack2(v.x, v.y);
        }
    }

    // ---- layer-0 CNOT ring: store layout C, gather permuted -> layout A ----
    // src(j) = j ^ (j>>1) ^ ((j&1) ? 0x300 : 0)
#pragma unroll
    for (int r = 0; r < R; r++) st[swz(idxC(r, tid))] = a[r];
    __syncthreads();
#pragma unroll
    for (int r = 0; r < R; r++) {
        const int j = (r << 6) | tid;
        int src = j ^ (j >> 1);
        if (j & 1) src ^= 0x300;
        a[r] = st[swz(src)];
    }

    // ---- layers 1, 2 ----
#pragma unroll 1
    for (int l = 1; l < NL; l++) {
        const u64* gb = gg + (l - 1) * NQ * 8;

        // Layout A: i-bits 9..6 in registers -> qubits 0..3
        apply_gate<3>(a, gb + 0 * 8);
        apply_gate<2>(a, gb + 1 * 8);
        apply_gate<1>(a, gb + 2 * 8);
        apply_gate<0>(a, gb + 3 * 8);

        // T1: A -> B  (B: i = (tid<<4) | r)
        __syncthreads();
#pragma unroll
        for (int r = 0; r < R; r++) st[swz((r << 6) | tid)] = a[r];
        __syncthreads();
#pragma unroll
        for (int r = 0; r < R; r++) a[r] = st[swz((tid << 4) | r)];

        // Layout B: i-bits 3..0 in registers -> qubits 9..6
        apply_gate<0>(a, gb + 9 * 8);
        apply_gate<1>(a, gb + 8 * 8);
        apply_gate<2>(a, gb + 7 * 8);
        apply_gate<3>(a, gb + 6 * 8);

        // T2: B -> C
        __syncthreads();
#pragma unroll
        for (int r = 0; r < R; r++) st[swz((tid << 4) | r)] = a[r];
        __syncthreads();
#pragma unroll
        for (int r = 0; r < R; r++) a[r] = st[swz(idxC(r, tid))];

        // Layout C: qubit 4 (i-bit 5 -> r-bit 1), qubit 5 (i-bit 4 -> r-bit 0)
        apply_gate<1>(a, gb + 4 * 8);
        apply_gate<0>(a, gb + 5 * 8);

        if (l == 1) {
            // T3: CNOT ring permutation back to layout A
            __syncthreads();
#pragma unroll
            for (int r = 0; r < R; r++) st[swz(idxC(r, tid))] = a[r];
            __syncthreads();
#pragma unroll
            for (int r = 0; r < R; r++) {
                const int j = (r << 6) | tid;
                int src = j ^ (j >> 1);
                if (j & 1) src ^= 0x300;
                a[r] = st[swz(src)];
            }
        }
    }

    // ---- readout in layout C with final CNOT ring folded into signs ----
    // sign for qubit q at index i: bit (9-q) of F(i), where
    //   F bits k=0..8: S_k = XOR of i-bits k..9;  F bit 9: b9 ^ S_0
    float z[NQ];
#pragma unroll
    for (int q = 0; q < NQ; q++) z[q] = 0.f;

#pragma unroll
    for (int r = 0; r < R; r++) {
        const int i = idxC(r, tid);
        float xx, yy; unpack2(mul2(a[r], a[r]), xx, yy);
        const float p = xx + yy;
        int s = (i >> 9) & 1;                     // S_9
#pragma unroll
        for (int k = 8; k >= 0; k--) {            // q = 9-k uses S_k
            s ^= (i >> k) & 1;
            z[9 - k] += s ? -p : p;
        }
        // q = 0 uses b9 ^ S_0 (s now holds S_0)
        z[0] += (((i >> 9) & 1) ^ s) ? -p : p;
    }

#pragma unroll
    for (int q = 0; q < NQ; q++) {
#pragma unroll
        for (int o = 16; o > 0; o >>= 1)
            z[q] += __shfl_xor_sync(0xffffffffu, z[q], o);
    }
    if ((tid & 31) == 0) {
#pragma unroll
        for (int q = 0; q < NQ; q++) wsum[tid >> 5][q] = z[q];
    }
    __syncthreads();
    if (tid < NQ) out[b * NQ + tid] = wsum[0][tid] + wsum[1][tid];
}

extern "C" void kernel_launch(void* const* d_in, const int* in_sizes, int n_in,
                              void* d_out, int out_size)
{
    const float* x = (const float*)d_in[0];       // (B, 10) float32
    const float* w = (const float*)d_in[1];       // (3, 10, 3) float32
    float* out = (float*)d_out;                   // (B, 10) float32
    const int B = in_sizes[0] / NQ;
    qnn_kernel<<<B, NT>>>(x, w, out);
}